// round 13
// baseline (speedup 1.0000x reference)
#include <cuda_runtime.h>
#include <math.h>

#define B_  2
#define S_  2048
#define T_  2048
#define D_  1024
#define H_  16
#define DK_ 64
#define DF_ 4096
#define BH_ (B_*H_)
#define M_  (B_*S_)   // 4096 rows for projections

// ---------------- static scratch (no allocations allowed) ----------------
__device__ float g_q  [M_ * D_];
__device__ float g_k  [M_ * D_];
__device__ float g_v  [M_ * D_];
__device__ float g_ctx[M_ * D_];
__device__ float g_o  [M_ * D_];
__device__ float g_x1 [M_ * D_];
__device__ float g_x2 [M_ * D_];
__device__ float g_ff [M_ * DF_];
__device__ float g_sc [(size_t)BH_ * S_ * S_];   // 512 MB scores

// ---------------- generic linear: C[M,N] = A[M,K] @ W[N,K]^T + b ----------------
// 128x128 tile, BK=8, 256 threads, 8x8 per thread
__global__ __launch_bounds__(256) void linear_kernel(
    const float* __restrict__ A, const float* __restrict__ W,
    const float* __restrict__ bias, float* __restrict__ C,
    int M, int N, int K, int relu)
{
    __shared__ float As[8][128];
    __shared__ float Bs[8][128];
    const int tid = threadIdx.x;
    const int m0 = blockIdx.y * 128;
    const int n0 = blockIdx.x * 128;
    const int ty = tid >> 4;      // 0..15
    const int tx = tid & 15;      // 0..15

    float acc[8][8];
#pragma unroll
    for (int i = 0; i < 8; i++)
#pragma unroll
        for (int j = 0; j < 8; j++) acc[i][j] = 0.f;

    const int lr = tid >> 1;          // 0..127
    const int lc = (tid & 1) * 4;     // 0 or 4
    const float* Ap = A + (size_t)(m0 + lr) * K + lc;
    const float* Wp = W + (size_t)(n0 + lr) * K + lc;

    for (int k0 = 0; k0 < K; k0 += 8) {
        float4 av = *(const float4*)(Ap + k0);
        float4 wv = *(const float4*)(Wp + k0);
        __syncthreads();
        As[lc + 0][lr] = av.x; As[lc + 1][lr] = av.y;
        As[lc + 2][lr] = av.z; As[lc + 3][lr] = av.w;
        Bs[lc + 0][lr] = wv.x; Bs[lc + 1][lr] = wv.y;
        Bs[lc + 2][lr] = wv.z; Bs[lc + 3][lr] = wv.w;
        __syncthreads();
#pragma unroll
        for (int kk = 0; kk < 8; kk++) {
            float a[8], b[8];
#pragma unroll
            for (int i = 0; i < 8; i++) a[i] = As[kk][ty * 8 + i];
#pragma unroll
            for (int j = 0; j < 8; j++) b[j] = Bs[kk][tx * 8 + j];
#pragma unroll
            for (int i = 0; i < 8; i++)
#pragma unroll
                for (int j = 0; j < 8; j++) acc[i][j] += a[i] * b[j];
        }
    }

#pragma unroll
    for (int i = 0; i < 8; i++) {
        const int m = m0 + ty * 8 + i;
#pragma unroll
        for (int j4 = 0; j4 < 8; j4 += 4) {
            const int n = n0 + tx * 8 + j4;
            float4 v;
            v.x = acc[i][j4 + 0] + bias[n + 0];
            v.y = acc[i][j4 + 1] + bias[n + 1];
            v.z = acc[i][j4 + 2] + bias[n + 2];
            v.w = acc[i][j4 + 3] + bias[n + 3];
            if (relu) {
                v.x = fmaxf(v.x, 0.f); v.y = fmaxf(v.y, 0.f);
                v.z = fmaxf(v.z, 0.f); v.w = fmaxf(v.w, 0.f);
            }
            *(float4*)(C + (size_t)m * N + n) = v;
        }
    }
}

// ---------------- attention scores: Sc[z,q,k] = (Q.K)/8 with mask ----------------
// 64x64 tile per block, 256 threads (16x16, 4x4/thread), K-dim = 64 in chunks of 16
__global__ __launch_bounds__(256) void scores_kernel(
    const float* __restrict__ Q, const float* __restrict__ Km,
    const int* __restrict__ mask, float* __restrict__ Sc,
    int Sq, int Skv, int maskMode)   // maskMode 0: mask[q*Skv+k] (causal), 1: mask[b*Skv+k]
{
    const int z = blockIdx.z;
    const int b = z / H_, h = z % H_;
    const int q0 = blockIdx.y * 64;
    const int k0 = blockIdx.x * 64;
    __shared__ float Qs[16][68];
    __shared__ float Ks[16][68];
    const int tid = threadIdx.x;
    const int ty = tid >> 4, tx = tid & 15;
    float acc[4][4];
#pragma unroll
    for (int i = 0; i < 4; i++)
#pragma unroll
        for (int j = 0; j < 4; j++) acc[i][j] = 0.f;

    const int lr = tid >> 2;          // 0..63
    const int lc = (tid & 3) * 4;     // 0,4,8,12
    const float* qb = Q + ((size_t)(b * Sq + q0 + lr)) * D_ + h * DK_ + lc;
    const float* kb = Km + ((size_t)(b * Skv + k0 + lr)) * D_ + h * DK_ + lc;

    for (int c0 = 0; c0 < DK_; c0 += 16) {
        float4 qv = *(const float4*)(qb + c0);
        float4 kv = *(const float4*)(kb + c0);
        __syncthreads();
        Qs[lc + 0][lr] = qv.x; Qs[lc + 1][lr] = qv.y;
        Qs[lc + 2][lr] = qv.z; Qs[lc + 3][lr] = qv.w;
        Ks[lc + 0][lr] = kv.x; Ks[lc + 1][lr] = kv.y;
        Ks[lc + 2][lr] = kv.z; Ks[lc + 3][lr] = kv.w;
        __syncthreads();
#pragma unroll
        for (int kk = 0; kk < 16; kk++) {
            float a[4], bb[4];
#pragma unroll
            for (int i = 0; i < 4; i++) a[i] = Qs[kk][ty * 4 + i];
#pragma unroll
            for (int j = 0; j < 4; j++) bb[j] = Ks[kk][tx * 4 + j];
#pragma unroll
            for (int i = 0; i < 4; i++)
#pragma unroll
                for (int j = 0; j < 4; j++) acc[i][j] += a[i] * bb[j];
        }
    }

#pragma unroll
    for (int i = 0; i < 4; i++) {
        const int qi = q0 + ty * 4 + i;
#pragma unroll
        for (int j = 0; j < 4; j++) {
            const int kj = k0 + tx * 4 + j;
            const int mv = (maskMode == 0) ? mask[(size_t)qi * Skv + kj]
                                           : mask[(size_t)b * Skv + kj];
            const float v = mv ? acc[i][j] * 0.125f : -INFINITY;
            Sc[((size_t)z * Sq + qi) * Skv + kj] = v;
        }
    }
}

// ---------------- row softmax over Skv=2048, 256 threads, 8 elems/thread ----------------
__global__ __launch_bounds__(256) void softmax_kernel(float* __restrict__ Sc, int Skv)
{
    __shared__ float red[256];
    const size_t row = blockIdx.x;
    float* p = Sc + row * (size_t)Skv;
    const int tid = threadIdx.x;
    float v[8];
    float mx = -INFINITY;
#pragma unroll
    for (int i = 0; i < 8; i++) { v[i] = p[tid + i * 256]; mx = fmaxf(mx, v[i]); }
    red[tid] = mx; __syncthreads();
    for (int s = 128; s > 0; s >>= 1) {
        if (tid < s) red[tid] = fmaxf(red[tid], red[tid + s]);
        __syncthreads();
    }
    mx = red[0]; __syncthreads();
    float sum = 0.f;
#pragma unroll
    for (int i = 0; i < 8; i++) { v[i] = __expf(v[i] - mx); sum += v[i]; }
    red[tid] = sum; __syncthreads();
    for (int s = 128; s > 0; s >>= 1) {
        if (tid < s) red[tid] += red[tid + s];
        __syncthreads();
    }
    const float inv = 1.f / red[0];
#pragma unroll
    for (int i = 0; i < 8; i++) p[tid + i * 256] = v[i] * inv;
}

// ---------------- attn @ V: O[b,q,h*64+d] = sum_k P[z,q,k] * V[b,k,h*64+d] ----------------
// 64q x 64d tile, 256 threads, 4x4/thread, K chunks of 16
__global__ __launch_bounds__(256) void attnv_kernel(
    const float* __restrict__ P, const float* __restrict__ V,
    float* __restrict__ O, int Sq, int Skv)
{
    const int z = blockIdx.y;
    const int b = z / H_, h = z % H_;
    const int q0 = blockIdx.x * 64;
    __shared__ float Ps[16][68];
    __shared__ float Vs[16][68];
    const int tid = threadIdx.x;
    const int ty = tid >> 4, tx = tid & 15;
    float acc[4][4];
#pragma unroll
    for (int i = 0; i < 4; i++)
#pragma unroll
        for (int j = 0; j < 4; j++) acc[i][j] = 0.f;

    const int pr = tid >> 2, pc = (tid & 3) * 4;   // P: 64 rows x 16 cols (transposed store)
    const int vr = tid >> 4, vc = (tid & 15) * 4;  // V: 16 rows x 64 cols (direct store)

    const float* pb = P + ((size_t)z * Sq + q0 + pr) * Skv + pc;
    const float* vb = V + ((size_t)b * Skv + vr) * D_ + h * DK_ + vc;

    for (int k0 = 0; k0 < Skv; k0 += 16) {
        float4 pv = *(const float4*)(pb + k0);
        float4 vv = *(const float4*)(vb + (size_t)k0 * D_);
        __syncthreads();
        Ps[pc + 0][pr] = pv.x; Ps[pc + 1][pr] = pv.y;
        Ps[pc + 2][pr] = pv.z; Ps[pc + 3][pr] = pv.w;
        *(float4*)&Vs[vr][vc] = vv;
        __syncthreads();
#pragma unroll
        for (int kk = 0; kk < 16; kk++) {
            float a[4], bb[4];
#pragma unroll
            for (int i = 0; i < 4; i++) a[i] = Ps[kk][ty * 4 + i];
#pragma unroll
            for (int j = 0; j < 4; j++) bb[j] = Vs[kk][tx * 4 + j];
#pragma unroll
            for (int i = 0; i < 4; i++)
#pragma unroll
                for (int j = 0; j < 4; j++) acc[i][j] += a[i] * bb[j];
        }
    }

#pragma unroll
    for (int i = 0; i < 4; i++) {
        const int qi = q0 + ty * 4 + i;
#pragma unroll
        for (int j = 0; j < 4; j++) {
            const int dj = h * DK_ + tx * 4 + j;
            O[((size_t)(b * Sq + qi)) * D_ + dj] = acc[i][j];
        }
    }
}

// ---------------- residual add + LayerNorm (two-pass, matches reference) ----------------
__global__ __launch_bounds__(256) void addln_kernel(
    const float* __restrict__ X, const float* __restrict__ Y,
    const float* __restrict__ g, const float* __restrict__ be,
    float* __restrict__ Out)
{
    __shared__ float red[256];
    const size_t row = blockIdx.x;
    const float* x = X + row * D_;
    const float* y = Y + row * D_;
    const int tid = threadIdx.x;
    float v[4];
    float s = 0.f;
#pragma unroll
    for (int i = 0; i < 4; i++) {
        v[i] = x[tid + i * 256] + y[tid + i * 256];
        s += v[i];
    }
    red[tid] = s; __syncthreads();
    for (int st = 128; st > 0; st >>= 1) {
        if (tid < st) red[tid] += red[tid + st];
        __syncthreads();
    }
    const float mu = red[0] * (1.f / D_); __syncthreads();
    float s2 = 0.f;
#pragma unroll
    for (int i = 0; i < 4; i++) { const float d = v[i] - mu; s2 += d * d; }
    red[tid] = s2; __syncthreads();
    for (int st = 128; st > 0; st >>= 1) {
        if (tid < st) red[tid] += red[tid + st];
        __syncthreads();
    }
    const float r = rsqrtf(red[0] * (1.f / D_) + 1e-5f);
#pragma unroll
    for (int i = 0; i < 4; i++) {
        const int c = tid + i * 256;
        Out[row * D_ + c] = (v[i] - mu) * r * g[c] + be[c];
    }
}

// ---------------- host orchestration ----------------
static float* symaddr(const void* sym)
{
    void* p = nullptr;
    cudaGetSymbolAddress(&p, sym);
    return (float*)p;
}

extern "C" void kernel_launch(void* const* d_in, const int* in_sizes, int n_in,
                              void* d_out, int out_size)
{
    const float* x       = (const float*)d_in[0];
    const float* enc     = (const float*)d_in[1];
    const int*   srcmask = (const int*)  d_in[2];
    const int*   tgtmask = (const int*)  d_in[3];
    const float* Wq1 = (const float*)d_in[4];  const float* bq1 = (const float*)d_in[5];
    const float* Wk1 = (const float*)d_in[6];  const float* bk1 = (const float*)d_in[7];
    const float* Wv1 = (const float*)d_in[8];  const float* bv1 = (const float*)d_in[9];
    const float* Wo1 = (const float*)d_in[10]; const float* bo1 = (const float*)d_in[11];
    const float* Wq2 = (const float*)d_in[12]; const float* bq2 = (const float*)d_in[13];
    const float* Wk2 = (const float*)d_in[14]; const float* bk2 = (const float*)d_in[15];
    const float* Wv2 = (const float*)d_in[16]; const float* bv2 = (const float*)d_in[17];
    const float* Wo2 = (const float*)d_in[18]; const float* bo2 = (const float*)d_in[19];
    const float* Wf1 = (const float*)d_in[20]; const float* bf1 = (const float*)d_in[21];
    const float* Wf2 = (const float*)d_in[22]; const float* bf2 = (const float*)d_in[23];
    const float* g1  = (const float*)d_in[24]; const float* be1 = (const float*)d_in[25];
    const float* g2  = (const float*)d_in[26]; const float* be2 = (const float*)d_in[27];
    const float* g3  = (const float*)d_in[28]; const float* be3 = (const float*)d_in[29];
    float* out = (float*)d_out;

    float* q  = symaddr(g_q);
    float* k  = symaddr(g_k);
    float* v  = symaddr(g_v);
    float* ctx= symaddr(g_ctx);
    float* o  = symaddr(g_o);
    float* x1 = symaddr(g_x1);
    float* x2 = symaddr(g_x2);
    float* ff = symaddr(g_ff);
    float* sc = symaddr(g_sc);

    const dim3 blk(256);
    const dim3 gLin1024(D_ / 128, M_ / 128);     // N=1024
    const dim3 gLinFF  (DF_ / 128, M_ / 128);    // N=4096
    const dim3 gScores (S_ / 64, S_ / 64, BH_);
    const dim3 gAttnV  (S_ / 64, BH_);
    const int  nSoftRows = BH_ * S_;

    // ---- self attention ----
    linear_kernel<<<gLin1024, blk>>>(x, Wq1, bq1, q, M_, D_, D_, 0);
    linear_kernel<<<gLin1024, blk>>>(x, Wk1, bk1, k, M_, D_, D_, 0);
    linear_kernel<<<gLin1024, blk>>>(x, Wv1, bv1, v, M_, D_, D_, 0);
    scores_kernel<<<gScores, blk>>>(q, k, tgtmask, sc, S_, S_, 0);
    softmax_kernel<<<nSoftRows, blk>>>(sc, S_);
    attnv_kernel<<<gAttnV, blk>>>(sc, v, ctx, S_, S_);
    linear_kernel<<<gLin1024, blk>>>(ctx, Wo1, bo1, o, M_, D_, D_, 0);
    addln_kernel<<<M_, blk>>>(x, o, g1, be1, x1);

    // ---- cross attention ----
    linear_kernel<<<gLin1024, blk>>>(x1,  Wq2, bq2, q, M_, D_, D_, 0);
    linear_kernel<<<gLin1024, blk>>>(enc, Wk2, bk2, k, B_ * T_, D_, D_, 0);
    linear_kernel<<<gLin1024, blk>>>(enc, Wv2, bv2, v, B_ * T_, D_, D_, 0);
    scores_kernel<<<gScores, blk>>>(q, k, srcmask, sc, S_, T_, 1);
    softmax_kernel<<<nSoftRows, blk>>>(sc, T_);
    attnv_kernel<<<gAttnV, blk>>>(sc, v, ctx, S_, T_);
    linear_kernel<<<gLin1024, blk>>>(ctx, Wo2, bo2, o, M_, D_, D_, 0);
    addln_kernel<<<M_, blk>>>(x1, o, g2, be2, x2);

    // ---- FFN ----
    linear_kernel<<<gLinFF, blk>>>(x2, Wf1, bf1, ff, M_, DF_, D_, 1);
    linear_kernel<<<gLin1024, blk>>>(ff, Wf2, bf2, o, M_, D_, DF_, 0);
    addln_kernel<<<M_, blk>>>(x2, o, g3, be3, out);
}

// round 14
// speedup vs baseline: 1.0007x; 1.0007x over previous
#include <cuda_runtime.h>
#include <math.h>

#define B_  2
#define S_  2048
#define T_  2048
#define D_  1024
#define H_  16
#define DK_ 64
#define DF_ 4096
#define BH_ (B_*H_)
#define M_  (B_*S_)   // 4096 rows for projections

// ---------------- static scratch (no allocations allowed) ----------------
__device__ float g_q  [M_ * D_];
__device__ float g_k  [M_ * D_];
__device__ float g_v  [M_ * D_];
__device__ float g_ctx[M_ * D_];
__device__ float g_o  [M_ * D_];
__device__ float g_x1 [M_ * D_];
__device__ float g_x2 [M_ * D_];
__device__ float g_ff [M_ * DF_];
__device__ float g_sc [(size_t)BH_ * S_ * S_];   // 512 MB scores

// ---------------- generic linear: C[M,N] = A[M,K] @ W[N,K]^T + b ----------------
// 128x128 tile, BK=8, 256 threads, 8x8 per thread
__global__ __launch_bounds__(256) void linear_kernel(
    const float* __restrict__ A, const float* __restrict__ W,
    const float* __restrict__ bias, float* __restrict__ C,
    int M, int N, int K, int relu)
{
    __shared__ float As[8][128];
    __shared__ float Bs[8][128];
    const int tid = threadIdx.x;
    const int m0 = blockIdx.y * 128;
    const int n0 = blockIdx.x * 128;
    const int ty = tid >> 4;      // 0..15
    const int tx = tid & 15;      // 0..15

    float acc[8][8];
#pragma unroll
    for (int i = 0; i < 8; i++)
#pragma unroll
        for (int j = 0; j < 8; j++) acc[i][j] = 0.f;

    const int lr = tid >> 1;          // 0..127
    const int lc = (tid & 1) * 4;     // 0 or 4
    const float* Ap = A + (size_t)(m0 + lr) * K + lc;
    const float* Wp = W + (size_t)(n0 + lr) * K + lc;

    for (int k0 = 0; k0 < K; k0 += 8) {
        float4 av = *(const float4*)(Ap + k0);
        float4 wv = *(const float4*)(Wp + k0);
        __syncthreads();
        As[lc + 0][lr] = av.x; As[lc + 1][lr] = av.y;
        As[lc + 2][lr] = av.z; As[lc + 3][lr] = av.w;
        Bs[lc + 0][lr] = wv.x; Bs[lc + 1][lr] = wv.y;
        Bs[lc + 2][lr] = wv.z; Bs[lc + 3][lr] = wv.w;
        __syncthreads();
#pragma unroll
        for (int kk = 0; kk < 8; kk++) {
            float a[8], b[8];
#pragma unroll
            for (int i = 0; i < 8; i++) a[i] = As[kk][ty * 8 + i];
#pragma unroll
            for (int j = 0; j < 8; j++) b[j] = Bs[kk][tx * 8 + j];
#pragma unroll
            for (int i = 0; i < 8; i++)
#pragma unroll
                for (int j = 0; j < 8; j++) acc[i][j] += a[i] * b[j];
        }
    }

#pragma unroll
    for (int i = 0; i < 8; i++) {
        const int m = m0 + ty * 8 + i;
#pragma unroll
        for (int j4 = 0; j4 < 8; j4 += 4) {
            const int n = n0 + tx * 8 + j4;
            float4 v;
            v.x = acc[i][j4 + 0] + bias[n + 0];
            v.y = acc[i][j4 + 1] + bias[n + 1];
            v.z = acc[i][j4 + 2] + bias[n + 2];
            v.w = acc[i][j4 + 3] + bias[n + 3];
            if (relu) {
                v.x = fmaxf(v.x, 0.f); v.y = fmaxf(v.y, 0.f);
                v.z = fmaxf(v.z, 0.f); v.w = fmaxf(v.w, 0.f);
            }
            *(float4*)(C + (size_t)m * N + n) = v;
        }
    }
}

// ---------------- attention scores: Sc[z,q,k] = (Q.K)/8 with mask ----------------
// 64x64 tile per block, 256 threads (16x16, 4x4/thread), K-dim = 64 in chunks of 16
__global__ __launch_bounds__(256) void scores_kernel(
    const float* __restrict__ Q, const float* __restrict__ Km,
    const int* __restrict__ mask, float* __restrict__ Sc,
    int Sq, int Skv, int maskMode)   // maskMode 0: mask[q*Skv+k] (causal), 1: mask[b*Skv+k]
{
    const int z = blockIdx.z;
    const int b = z / H_, h = z % H_;
    const int q0 = blockIdx.y * 64;
    const int k0 = blockIdx.x * 64;
    __shared__ float Qs[16][68];
    __shared__ float Ks[16][68];
    const int tid = threadIdx.x;
    const int ty = tid >> 4, tx = tid & 15;
    float acc[4][4];
#pragma unroll
    for (int i = 0; i < 4; i++)
#pragma unroll
        for (int j = 0; j < 4; j++) acc[i][j] = 0.f;

    const int lr = tid >> 2;          // 0..63
    const int lc = (tid & 3) * 4;     // 0,4,8,12
    const float* qb = Q + ((size_t)(b * Sq + q0 + lr)) * D_ + h * DK_ + lc;
    const float* kb = Km + ((size_t)(b * Skv + k0 + lr)) * D_ + h * DK_ + lc;

    for (int c0 = 0; c0 < DK_; c0 += 16) {
        float4 qv = *(const float4*)(qb + c0);
        float4 kv = *(const float4*)(kb + c0);
        __syncthreads();
        Qs[lc + 0][lr] = qv.x; Qs[lc + 1][lr] = qv.y;
        Qs[lc + 2][lr] = qv.z; Qs[lc + 3][lr] = qv.w;
        Ks[lc + 0][lr] = kv.x; Ks[lc + 1][lr] = kv.y;
        Ks[lc + 2][lr] = kv.z; Ks[lc + 3][lr] = kv.w;
        __syncthreads();
#pragma unroll
        for (int kk = 0; kk < 16; kk++) {
            float a[4], bb[4];
#pragma unroll
            for (int i = 0; i < 4; i++) a[i] = Qs[kk][ty * 4 + i];
#pragma unroll
            for (int j = 0; j < 4; j++) bb[j] = Ks[kk][tx * 4 + j];
#pragma unroll
            for (int i = 0; i < 4; i++)
#pragma unroll
                for (int j = 0; j < 4; j++) acc[i][j] += a[i] * bb[j];
        }
    }

#pragma unroll
    for (int i = 0; i < 4; i++) {
        const int qi = q0 + ty * 4 + i;
#pragma unroll
        for (int j = 0; j < 4; j++) {
            const int kj = k0 + tx * 4 + j;
            const int mv = (maskMode == 0) ? mask[(size_t)qi * Skv + kj]
                                           : mask[(size_t)b * Skv + kj];
            const float v = mv ? acc[i][j] * 0.125f : -INFINITY;
            Sc[((size_t)z * Sq + qi) * Skv + kj] = v;
        }
    }
}

// ---------------- row softmax over Skv=2048, 256 threads, 8 elems/thread ----------------
__global__ __launch_bounds__(256) void softmax_kernel(float* __restrict__ Sc, int Skv)
{
    __shared__ float red[256];
    const size_t row = blockIdx.x;
    float* p = Sc + row * (size_t)Skv;
    const int tid = threadIdx.x;
    float v[8];
    float mx = -INFINITY;
#pragma unroll
    for (int i = 0; i < 8; i++) { v[i] = p[tid + i * 256]; mx = fmaxf(mx, v[i]); }
    red[tid] = mx; __syncthreads();
    for (int s = 128; s > 0; s >>= 1) {
        if (tid < s) red[tid] = fmaxf(red[tid], red[tid + s]);
        __syncthreads();
    }
    mx = red[0]; __syncthreads();
    float sum = 0.f;
#pragma unroll
    for (int i = 0; i < 8; i++) { v[i] = __expf(v[i] - mx); sum += v[i]; }
    red[tid] = sum; __syncthreads();
    for (int s = 128; s > 0; s >>= 1) {
        if (tid < s) red[tid] += red[tid + s];
        __syncthreads();
    }
    const float inv = 1.f / red[0];
#pragma unroll
    for (int i = 0; i < 8; i++) p[tid + i * 256] = v[i] * inv;
}

// ---------------- attn @ V: O[b,q,h*64+d] = sum_k P[z,q,k] * V[b,k,h*64+d] ----------------
// 64q x 64d tile, 256 threads, 4x4/thread, K chunks of 16
__global__ __launch_bounds__(256) void attnv_kernel(
    const float* __restrict__ P, const float* __restrict__ V,
    float* __restrict__ O, int Sq, int Skv)
{
    const int z = blockIdx.y;
    const int b = z / H_, h = z % H_;
    const int q0 = blockIdx.x * 64;
    __shared__ float Ps[16][68];
    __shared__ float Vs[16][68];
    const int tid = threadIdx.x;
    const int ty = tid >> 4, tx = tid & 15;
    float acc[4][4];
#pragma unroll
    for (int i = 0; i < 4; i++)
#pragma unroll
        for (int j = 0; j < 4; j++) acc[i][j] = 0.f;

    const int pr = tid >> 2, pc = (tid & 3) * 4;   // P: 64 rows x 16 cols (transposed store)
    const int vr = tid >> 4, vc = (tid & 15) * 4;  // V: 16 rows x 64 cols (direct store)

    const float* pb = P + ((size_t)z * Sq + q0 + pr) * Skv + pc;
    const float* vb = V + ((size_t)b * Skv + vr) * D_ + h * DK_ + vc;

    for (int k0 = 0; k0 < Skv; k0 += 16) {
        float4 pv = *(const float4*)(pb + k0);
        float4 vv = *(const float4*)(vb + (size_t)k0 * D_);
        __syncthreads();
        Ps[pc + 0][pr] = pv.x; Ps[pc + 1][pr] = pv.y;
        Ps[pc + 2][pr] = pv.z; Ps[pc + 3][pr] = pv.w;
        *(float4*)&Vs[vr][vc] = vv;
        __syncthreads();
#pragma unroll
        for (int kk = 0; kk < 16; kk++) {
            float a[4], bb[4];
#pragma unroll
            for (int i = 0; i < 4; i++) a[i] = Ps[kk][ty * 4 + i];
#pragma unroll
            for (int j = 0; j < 4; j++) bb[j] = Vs[kk][tx * 4 + j];
#pragma unroll
            for (int i = 0; i < 4; i++)
#pragma unroll
                for (int j = 0; j < 4; j++) acc[i][j] += a[i] * bb[j];
        }
    }

#pragma unroll
    for (int i = 0; i < 4; i++) {
        const int qi = q0 + ty * 4 + i;
#pragma unroll
        for (int j = 0; j < 4; j++) {
            const int dj = h * DK_ + tx * 4 + j;
            O[((size_t)(b * Sq + qi)) * D_ + dj] = acc[i][j];
        }
    }
}

// ---------------- residual add + LayerNorm (two-pass, matches reference) ----------------
__global__ __launch_bounds__(256) void addln_kernel(
    const float* __restrict__ X, const float* __restrict__ Y,
    const float* __restrict__ g, const float* __restrict__ be,
    float* __restrict__ Out)
{
    __shared__ float red[256];
    const size_t row = blockIdx.x;
    const float* x = X + row * D_;
    const float* y = Y + row * D_;
    const int tid = threadIdx.x;
    float v[4];
    float s = 0.f;
#pragma unroll
    for (int i = 0; i < 4; i++) {
        v[i] = x[tid + i * 256] + y[tid + i * 256];
        s += v[i];
    }
    red[tid] = s; __syncthreads();
    for (int st = 128; st > 0; st >>= 1) {
        if (tid < st) red[tid] += red[tid + st];
        __syncthreads();
    }
    const float mu = red[0] * (1.f / D_); __syncthreads();
    float s2 = 0.f;
#pragma unroll
    for (int i = 0; i < 4; i++) { const float d = v[i] - mu; s2 += d * d; }
    red[tid] = s2; __syncthreads();
    for (int st = 128; st > 0; st >>= 1) {
        if (tid < st) red[tid] += red[tid + st];
        __syncthreads();
    }
    const float r = rsqrtf(red[0] * (1.f / D_) + 1e-5f);
#pragma unroll
    for (int i = 0; i < 4; i++) {
        const int c = tid + i * 256;
        Out[row * D_ + c] = (v[i] - mu) * r * g[c] + be[c];
    }
}

// ---------------- host orchestration ----------------
static float* symaddr(const void* sym)
{
    void* p = nullptr;
    cudaGetSymbolAddress(&p, sym);
    return (float*)p;
}

extern "C" void kernel_launch(void* const* d_in, const int* in_sizes, int n_in,
                              void* d_out, int out_size)
{
    const float* x       = (const float*)d_in[0];
    const float* enc     = (const float*)d_in[1];
    const int*   srcmask = (const int*)  d_in[2];
    const int*   tgtmask = (const int*)  d_in[3];
    const float* Wq1 = (const float*)d_in[4];  const float* bq1 = (const float*)d_in[5];
    const float* Wk1 = (const float*)d_in[6];  const float* bk1 = (const float*)d_in[7];
    const float* Wv1 = (const float*)d_in[8];  const float* bv1 = (const float*)d_in[9];
    const float* Wo1 = (const float*)d_in[10]; const float* bo1 = (const float*)d_in[11];
    const float* Wq2 = (const float*)d_in[12]; const float* bq2 = (const float*)d_in[13];
    const float* Wk2 = (const float*)d_in[14]; const float* bk2 = (const float*)d_in[15];
    const float* Wv2 = (const float*)d_in[16]; const float* bv2 = (const float*)d_in[17];
    const float* Wo2 = (const float*)d_in[18]; const float* bo2 = (const float*)d_in[19];
    const float* Wf1 = (const float*)d_in[20]; const float* bf1 = (const float*)d_in[21];
    const float* Wf2 = (const float*)d_in[22]; const float* bf2 = (const float*)d_in[23];
    const float* g1  = (const float*)d_in[24]; const float* be1 = (const float*)d_in[25];
    const float* g2  = (const float*)d_in[26]; const float* be2 = (const float*)d_in[27];
    const float* g3  = (const float*)d_in[28]; const float* be3 = (const float*)d_in[29];
    float* out = (float*)d_out;

    float* q  = symaddr(g_q);
    float* k  = symaddr(g_k);
    float* v  = symaddr(g_v);
    float* ctx= symaddr(g_ctx);
    float* o  = symaddr(g_o);
    float* x1 = symaddr(g_x1);
    float* x2 = symaddr(g_x2);
    float* ff = symaddr(g_ff);
    float* sc = symaddr(g_sc);

    const dim3 blk(256);
    const dim3 gLin1024(D_ / 128, M_ / 128);     // N=1024
    const dim3 gLinFF  (DF_ / 128, M_ / 128);    // N=4096
    const dim3 gScores (S_ / 64, S_ / 64, BH_);
    const dim3 gAttnV  (S_ / 64, BH_);
    const int  nSoftRows = BH_ * S_;

    // ---- self attention ----
    linear_kernel<<<gLin1024, blk>>>(x, Wq1, bq1, q, M_, D_, D_, 0);
    linear_kernel<<<gLin1024, blk>>>(x, Wk1, bk1, k, M_, D_, D_, 0);
    linear_kernel<<<gLin1024, blk>>>(x, Wv1, bv1, v, M_, D_, D_, 0);
    scores_kernel<<<gScores, blk>>>(q, k, tgtmask, sc, S_, S_, 0);
    softmax_kernel<<<nSoftRows, blk>>>(sc, S_);
    attnv_kernel<<<gAttnV, blk>>>(sc, v, ctx, S_, S_);
    linear_kernel<<<gLin1024, blk>>>(ctx, Wo1, bo1, o, M_, D_, D_, 0);
    addln_kernel<<<M_, blk>>>(x, o, g1, be1, x1);

    // ---- cross attention ----
    linear_kernel<<<gLin1024, blk>>>(x1,  Wq2, bq2, q, M_, D_, D_, 0);
    linear_kernel<<<gLin1024, blk>>>(enc, Wk2, bk2, k, B_ * T_, D_, D_, 0);
    linear_kernel<<<gLin1024, blk>>>(enc, Wv2, bv2, v, B_ * T_, D_, D_, 0);
    scores_kernel<<<gScores, blk>>>(q, k, srcmask, sc, S_, T_, 1);
    softmax_kernel<<<nSoftRows, blk>>>(sc, T_);
    attnv_kernel<<<gAttnV, blk>>>(sc, v, ctx, S_, T_);
    linear_kernel<<<gLin1024, blk>>>(ctx, Wo2, bo2, o, M_, D_, D_, 0);
    addln_kernel<<<M_, blk>>>(x1, o, g2, be2, x2);

    // ---- FFN ----
    linear_kernel<<<gLinFF, blk>>>(x2, Wf1, bf1, ff, M_, DF_, D_, 1);
    linear_kernel<<<gLin1024, blk>>>(ff, Wf2, bf2, o, M_, D_, DF_, 0);
    addln_kernel<<<M_, blk>>>(x2, o, g3, be3, out);
}